// round 13
// baseline (speedup 1.0000x reference)
#include <cuda_runtime.h>
#include <cuda_fp16.h>
#include <cstdint>

#define D_DIM 64
#define K_DIM 512
#define TILE_ROWS 128
#define THREADS 512
#define NBLOCKS 148
#define MARGIN 0.6f

// ---------------- device scratch (no cudaMalloc allowed) ----------------
__device__ float g_Et[K_DIM * D_DIM];    // exact fp32 E, code-major [k][d]

// ---------------- smem layout (bytes) ----------------
#define SM_EH    0                                   // [64][512] half  = 65536
#define SM_XH    (SM_EH + D_DIM * K_DIM * 2)         // [128][64] half2 = 32768 (dup -2x)
#define SM_XF    (SM_XH + TILE_ROWS * D_DIM * 4)     // [128][64] f32   = 32768
#define SM_SE2   (SM_XF + TILE_ROWS * D_DIM * 4)     // [512] f32       = 2048
#define SM_KFIN  (SM_SE2 + K_DIM * 4)                // [128] i32       = 512
#define SM_TOTAL (SM_KFIN + TILE_ROWS * 4)           // 133632

// ---------------- prep: transpose E to code-major ----------------
__global__ void vq_prep(const float* __restrict__ emb) {
    int i = blockIdx.x * blockDim.x + threadIdx.x;
    if (i < K_DIM * D_DIM) {
        int k = i / D_DIM, d = i % D_DIM;
        g_Et[i] = emb[d * K_DIM + k];
    }
}

// exact fp32 distance: x row from smem, E row from gmem (L2-hot)
__device__ __forceinline__ float exact_dist(const float* xr, int k, float se2k) {
    const float4* er = (const float4*)(g_Et + k * D_DIM);
    const float4* x4 = (const float4*)xr;
    float d0 = 0.f, d1 = 0.f;
    #pragma unroll 4
    for (int q = 0; q < 16; q += 2) {
        float4 ea = er[q],     xa = x4[q];
        float4 eb = er[q + 1], xb = x4[q + 1];
        d0 = fmaf(xa.x, ea.x, d0); d0 = fmaf(xa.y, ea.y, d0);
        d0 = fmaf(xa.z, ea.z, d0); d0 = fmaf(xa.w, ea.w, d0);
        d1 = fmaf(xb.x, eb.x, d1); d1 = fmaf(xb.y, eb.y, d1);
        d1 = fmaf(xb.z, eb.z, d1); d1 = fmaf(xb.w, eb.w, d1);
    }
    return fmaf(-2.f, d0 + d1, se2k);
}

// ---------------- main ----------------
__global__ void __launch_bounds__(THREADS, 1)
vq_main(const float* __restrict__ x, const float* __restrict__ emb,
        float* __restrict__ out, int nrows, int ntiles)
{
    extern __shared__ char smem[];
    __half*  sEh  = (__half*) (smem + SM_EH);    // [d][k] fp16 codebook
    __half2* sxh  = (__half2*)(smem + SM_XH);    // [row][d] dup {-2x,-2x}
    float*   sxf  = (float*)  (smem + SM_XF);    // [row][d] exact x
    float*   se2s = (float*)  (smem + SM_SE2);
    int*     kfin = (int*)    (smem + SM_KFIN);

    const int tid  = threadIdx.x;
    const int warp = tid >> 5;
    const int lane = tid & 31;
    const int r0   = warp * 8;            // 8 rows per warp, 16 warps -> 128 rows

    // ---- one-time: fp16 codebook (emb is already [d][k]) + exact ||e||^2 ----
    for (int i = tid; i < D_DIM * K_DIM / 4; i += THREADS) {
        float4 v = *(const float4*)(emb + i * 4);
        __half2 h0 = __floats2half2_rn(v.x, v.y);
        __half2 h1 = __floats2half2_rn(v.z, v.w);
        uint2 pk;
        pk.x = *(uint32_t*)&h0; pk.y = *(uint32_t*)&h1;
        *(uint2*)(sEh + i * 4) = pk;
    }
    {
        const float* er = g_Et + tid * D_DIM;    // THREADS == K_DIM
        float s = 0.f;
        #pragma unroll 8
        for (int d = 0; d < D_DIM; d++) s = fmaf(er[d], er[d], s);
        se2s[tid] = s;
    }
    __syncthreads();

    for (int tile = blockIdx.x; tile < ntiles; tile += gridDim.x) {
        const int rowbase = tile * TILE_ROWS;

        // ---- load x tile: exact fp32 + dup'd fp16 (-2x) ----
        for (int i = tid; i < TILE_ROWS * D_DIM / 4; i += THREADS) {
            int row = i >> 4, d4 = (i & 15) * 4;
            int grow = rowbase + row;
            float4 v = (grow < nrows) ? *(const float4*)(x + (size_t)grow * D_DIM + d4)
                                      : make_float4(0.f, 0.f, 0.f, 0.f);
            *(float4*)(sxf + row * D_DIM + d4) = v;
            __half2 a = __floats2half2_rn(-2.f * v.x, -2.f * v.x);
            __half2 b = __floats2half2_rn(-2.f * v.y, -2.f * v.y);
            __half2 c = __floats2half2_rn(-2.f * v.z, -2.f * v.z);
            __half2 e = __floats2half2_rn(-2.f * v.w, -2.f * v.w);
            uint4 pk;
            pk.x = *(uint32_t*)&a; pk.y = *(uint32_t*)&b;
            pk.z = *(uint32_t*)&c; pk.w = *(uint32_t*)&e;
            *(uint4*)(sxh + row * D_DIM + d4) = pk;
        }
        __syncthreads();

        // ---- HFMA2 mainloop: per-lane best + second-best tracking ----
        float bestv[8], secv[8]; int bidx[8];
        #pragma unroll
        for (int r = 0; r < 8; r++) { bestv[r] = 3.4e38f; secv[r] = 3.4e38f; bidx[r] = 0; }

        #pragma unroll
        for (int p = 0; p < 2; p++) {
            const int kbase = p * 256 + lane * 8;    // lane owns 8 consecutive codes

            __half2 acc[8][4];
            const __half2 z = __floats2half2_rn(0.f, 0.f);
            #pragma unroll
            for (int r = 0; r < 8; r++) {
                acc[r][0] = z; acc[r][1] = z; acc[r][2] = z; acc[r][3] = z;
            }

            const __half* ebase = sEh + kbase;
            #pragma unroll 4
            for (int d = 0; d < D_DIM; d++) {
                uint4 ew = *(const uint4*)(ebase + d * K_DIM);   // 8 fp16 codes, conflict-free
                __half2 e0 = *(__half2*)&ew.x, e1 = *(__half2*)&ew.y;
                __half2 e2 = *(__half2*)&ew.z, e3 = *(__half2*)&ew.w;
                #pragma unroll
                for (int r = 0; r < 8; r++) {
                    __half2 xr = sxh[(r0 + r) * D_DIM + d];      // broadcast LDS.32
                    acc[r][0] = __hfma2(e0, xr, acc[r][0]);
                    acc[r][1] = __hfma2(e1, xr, acc[r][1]);
                    acc[r][2] = __hfma2(e2, xr, acc[r][2]);
                    acc[r][3] = __hfma2(e3, xr, acc[r][3]);
                }
            }

            float4 s2a = *(const float4*)(se2s + kbase);
            float4 s2b = *(const float4*)(se2s + kbase + 4);
            #pragma unroll
            for (int r = 0; r < 8; r++) {
                float2 f0 = __half22float2(acc[r][0]);
                float2 f1 = __half22float2(acc[r][1]);
                float2 f2 = __half22float2(acc[r][2]);
                float2 f3 = __half22float2(acc[r][3]);
                float s[8] = { f0.x + s2a.x, f0.y + s2a.y, f1.x + s2a.z, f1.y + s2a.w,
                               f2.x + s2b.x, f2.y + s2b.y, f3.x + s2b.z, f3.y + s2b.w };
                #pragma unroll
                for (int j = 0; j < 8; j++) {
                    if (s[j] < bestv[r]) { secv[r] = bestv[r]; bestv[r] = s[j]; bidx[r] = kbase + j; }
                    else if (s[j] < secv[r]) secv[r] = s[j];
                }
            }
        }

        // ---- per-row resolve: approx min -> complete candidate set -> exact pick ----
        #pragma unroll 1
        for (int r = 0; r < 8; r++) {
            float mv = bestv[r];
            #pragma unroll
            for (int off = 16; off; off >>= 1)
                mv = fminf(mv, __shfl_xor_sync(0xffffffffu, mv, off));
            const float thr = mv + MARGIN;

            // if any lane might be hiding a candidate behind its best -> full exact scan
            unsigned hid = __ballot_sync(0xffffffffu, secv[r] <= thr);
            const float* xr = sxf + (r0 + r) * D_DIM;

            float ev = 3.4e38f; int ek = 0x7fffffff;
            if (hid == 0) {
                if (bestv[r] <= thr) { ek = bidx[r]; ev = exact_dist(xr, ek, se2s[ek]); }
            } else {
                #pragma unroll 1
                for (int j = 0; j < 16; j++) {
                    int k = lane * 16 + j;
                    float s = exact_dist(xr, k, se2s[k]);
                    if (s < ev || (s == ev && k < ek)) { ev = s; ek = k; }
                }
            }
            #pragma unroll
            for (int off = 16; off; off >>= 1) {
                float ov = __shfl_xor_sync(0xffffffffu, ev, off);
                int   ok = __shfl_xor_sync(0xffffffffu, ek, off);
                if (ov < ev || (ov == ev && ok < ek)) { ev = ov; ek = ok; }
            }
            if (lane == 0) kfin[r0 + r] = ek;
        }
        __syncthreads();

        // ---- gather exact E row + store (4 threads/row x 16 floats) ----
        {
            int row = tid >> 2, part = tid & 3;
            int grow = rowbase + row;
            if (grow < nrows) {
                const float4* src = (const float4*)(g_Et + kfin[row] * D_DIM + part * 16);
                float4* dst = (float4*)(out + (size_t)grow * D_DIM + part * 16);
                dst[0] = src[0]; dst[1] = src[1]; dst[2] = src[2]; dst[3] = src[3];
            }
        }
        __syncthreads();   // sxf/sxh/kfin reuse guard for next tile
    }
}

extern "C" void kernel_launch(void* const* d_in, const int* in_sizes, int n_in,
                              void* d_out, int out_size)
{
    const float* x   = (const float*)d_in[0];   // inputs [B,H,W,D] fp32
    const float* emb = (const float*)d_in[1];   // embeddings [D,K] fp32
    float* out = (float*)d_out;

    int nrows  = in_sizes[0] / D_DIM;
    int ntiles = (nrows + TILE_ROWS - 1) / TILE_ROWS;

    vq_prep<<<(K_DIM * D_DIM + 511) / 512, 512>>>(emb);

    cudaFuncSetAttribute(vq_main, cudaFuncAttributeMaxDynamicSharedMemorySize, SM_TOTAL);
    int grid = NBLOCKS;
    if (grid > ntiles) grid = ntiles;
    vq_main<<<grid, THREADS, SM_TOTAL>>>(x, emb, out, nrows, ntiles);
}

// round 14
// speedup vs baseline: 1.8268x; 1.8268x over previous
#include <cuda_runtime.h>
#include <cuda_fp16.h>
#include <cstdint>

#define D_DIM 64
#define K_DIM 512
#define TILE_ROWS 64
#define THREADS 512
#define NBLOCKS 148
#define MARGIN 1.0f
#define DPITCH_H 520     // dist pitch in halves (1040 B)

// ---------------- device scratch (no cudaMalloc allowed) ----------------
__device__ float g_Et[K_DIM * D_DIM];    // exact fp32 E, code-major [k][d]

// ---------------- smem layout (bytes) ----------------
#define SM_EH    0                                    // [64][512] half  = 65536
#define SM_XH    (SM_EH + D_DIM * K_DIM * 2)          // [64][64] half2  = 16384 (dup -2x)
#define SM_XF    (SM_XH + TILE_ROWS * D_DIM * 4)      // [64][64] f32    = 16384
#define SM_SE2   (SM_XF + TILE_ROWS * D_DIM * 4)      // [512] f32       = 2048
#define SM_PVAL  (SM_SE2 + K_DIM * 4)                 // [2][64] f32     = 512
#define SM_RTHR  (SM_PVAL + 512)                      // [64] f32        = 256
#define SM_KFIN  (SM_RTHR + 256)                      // [64] i32        = 256
#define SM_DIST  (SM_KFIN + 256)                      // [64][520] half  = 66560
#define SM_TOTAL (SM_DIST + TILE_ROWS * DPITCH_H * 2) // 167936

// ---------------- prep: transpose E to code-major ----------------
__global__ void vq_prep(const float* __restrict__ emb) {
    int i = blockIdx.x * blockDim.x + threadIdx.x;
    if (i < K_DIM * D_DIM) {
        int k = i / D_DIM, d = i % D_DIM;
        g_Et[i] = emb[d * K_DIM + k];
    }
}

// exact fp32 distance: x row from smem, E row from gmem (L2-hot)
__device__ __forceinline__ float exact_dist(const float* xr, int k, float se2k) {
    const float4* er = (const float4*)(g_Et + k * D_DIM);
    const float4* x4 = (const float4*)xr;
    float d0 = 0.f, d1 = 0.f;
    #pragma unroll 4
    for (int q = 0; q < 16; q += 2) {
        float4 ea = er[q],     xa = x4[q];
        float4 eb = er[q + 1], xb = x4[q + 1];
        d0 = fmaf(xa.x, ea.x, d0); d0 = fmaf(xa.y, ea.y, d0);
        d0 = fmaf(xa.z, ea.z, d0); d0 = fmaf(xa.w, ea.w, d0);
        d1 = fmaf(xb.x, eb.x, d1); d1 = fmaf(xb.y, eb.y, d1);
        d1 = fmaf(xb.z, eb.z, d1); d1 = fmaf(xb.w, eb.w, d1);
    }
    return fmaf(-2.f, d0 + d1, se2k);
}

// ---------------- main ----------------
__global__ void __launch_bounds__(THREADS, 1)
vq_main(const float* __restrict__ x, const float* __restrict__ emb,
        float* __restrict__ out, int nrows, int ntiles)
{
    extern __shared__ char smem[];
    __half*  sEh  = (__half*) (smem + SM_EH);    // [d][k] fp16 codebook
    __half2* sxh  = (__half2*)(smem + SM_XH);    // [row][d] dup {-2x,-2x}
    float*   sxf  = (float*)  (smem + SM_XF);    // [row][d] exact x
    float*   se2s = (float*)  (smem + SM_SE2);
    float*   pval = (float*)  (smem + SM_PVAL);  // [2][64]
    float*   rthr = (float*)  (smem + SM_RTHR);
    int*     kfin = (int*)    (smem + SM_KFIN);
    __half*  dist = (__half*) (smem + SM_DIST);  // raw -2x.e accumulators

    const int tid  = threadIdx.x;
    const int warp = tid >> 5;
    const int lane = tid & 31;
    const int g    = warp & 7;            // row group: rows g*8..+7
    const int h    = warp >> 3;           // K half: codes h*256..+255
    const int r0   = g * 8;
    const int kbase = h * 256 + lane * 8; // lane owns 8 consecutive codes

    // ---- one-time: fp16 codebook (emb is already [d][k]) + exact ||e||^2 ----
    for (int i = tid; i < D_DIM * K_DIM / 4; i += THREADS) {
        float4 v = *(const float4*)(emb + i * 4);
        __half2 h0 = __floats2half2_rn(v.x, v.y);
        __half2 h1 = __floats2half2_rn(v.z, v.w);
        uint2 pk;
        pk.x = *(uint32_t*)&h0; pk.y = *(uint32_t*)&h1;
        *(uint2*)(sEh + i * 4) = pk;
    }
    {
        const float* er = g_Et + tid * D_DIM;    // THREADS == K_DIM
        float s = 0.f;
        #pragma unroll 8
        for (int d = 0; d < D_DIM; d++) s = fmaf(er[d], er[d], s);
        se2s[tid] = s;
    }
    __syncthreads();

    for (int tile = blockIdx.x; tile < ntiles; tile += gridDim.x) {
        const int rowbase = tile * TILE_ROWS;

        // ---- load x tile: exact fp32 + dup'd fp16 (-2x) ----
        for (int i = tid; i < TILE_ROWS * D_DIM / 4; i += THREADS) {
            int row = i >> 4, d4 = (i & 15) * 4;
            int grow = rowbase + row;
            float4 v = (grow < nrows) ? *(const float4*)(x + (size_t)grow * D_DIM + d4)
                                      : make_float4(0.f, 0.f, 0.f, 0.f);
            *(float4*)(sxf + row * D_DIM + d4) = v;
            __half2 a = __floats2half2_rn(-2.f * v.x, -2.f * v.x);
            __half2 b = __floats2half2_rn(-2.f * v.y, -2.f * v.y);
            __half2 c = __floats2half2_rn(-2.f * v.z, -2.f * v.z);
            __half2 e = __floats2half2_rn(-2.f * v.w, -2.f * v.w);
            uint4 pk;
            pk.x = *(uint32_t*)&a; pk.y = *(uint32_t*)&b;
            pk.z = *(uint32_t*)&c; pk.w = *(uint32_t*)&e;
            *(uint4*)(sxh + row * D_DIM + d4) = pk;
        }
        __syncthreads();

        // ---- HFMA2 mainloop: warp = 8 rows x 256 codes, lane = 8 codes ----
        __half2 acc[8][4];
        const __half2 z = __floats2half2_rn(0.f, 0.f);
        #pragma unroll
        for (int r = 0; r < 8; r++) {
            acc[r][0] = z; acc[r][1] = z; acc[r][2] = z; acc[r][3] = z;
        }

        const __half* ebase = sEh + kbase;
        #pragma unroll 4
        for (int d = 0; d < D_DIM; d++) {
            uint4 ew = *(const uint4*)(ebase + d * K_DIM);   // 8 fp16 codes, conflict-free
            __half2 e0 = *(__half2*)&ew.x, e1 = *(__half2*)&ew.y;
            __half2 e2 = *(__half2*)&ew.z, e3 = *(__half2*)&ew.w;
            #pragma unroll
            for (int r = 0; r < 8; r++) {
                __half2 xr = sxh[(r0 + r) * D_DIM + d];      // broadcast LDS.32
                acc[r][0] = __hfma2(e0, xr, acc[r][0]);
                acc[r][1] = __hfma2(e1, xr, acc[r][1]);
                acc[r][2] = __hfma2(e2, xr, acc[r][2]);
                acc[r][3] = __hfma2(e3, xr, acc[r][3]);
            }
        }

        // store raw accumulators to dist (16B per row per lane, conflict-free)
        // and track per-lane approx best VALUE per row
        float bestv[8];
        {
            float4 s2a = *(const float4*)(se2s + kbase);
            float4 s2b = *(const float4*)(se2s + kbase + 4);
            #pragma unroll
            for (int r = 0; r < 8; r++) {
                uint4 pk;
                pk.x = *(uint32_t*)&acc[r][0]; pk.y = *(uint32_t*)&acc[r][1];
                pk.z = *(uint32_t*)&acc[r][2]; pk.w = *(uint32_t*)&acc[r][3];
                *(uint4*)(dist + (r0 + r) * DPITCH_H + kbase) = pk;

                float2 f0 = __half22float2(acc[r][0]);
                float2 f1 = __half22float2(acc[r][1]);
                float2 f2 = __half22float2(acc[r][2]);
                float2 f3 = __half22float2(acc[r][3]);
                float m = fminf(fminf(f0.x + s2a.x, f0.y + s2a.y),
                                fminf(f1.x + s2a.z, f1.y + s2a.w));
                m = fminf(m, fminf(fminf(f2.x + s2b.x, f2.y + s2b.y),
                                   fminf(f3.x + s2b.z, f3.y + s2b.w)));
                bestv[r] = m;
            }
        }
        // per-row warp-reduce best value; write pval[h][row]
        #pragma unroll
        for (int r = 0; r < 8; r++) {
            float mv = bestv[r];
            #pragma unroll
            for (int off = 16; off; off >>= 1)
                mv = fminf(mv, __shfl_xor_sync(0xffffffffu, mv, off));
            if (lane == 0) pval[h * 64 + r0 + r] = mv;
        }
        __syncthreads();

        // merge the two K-halves -> per-row threshold
        if (tid < TILE_ROWS)
            rthr[tid] = fminf(pval[tid], pval[64 + tid]) + MARGIN;
        __syncthreads();

        // ---- scan: candidates from stored scores, exact fp32 rescore ----
        // warp -> 4 rows; lane -> 16 codes of that row
        for (int rr = 0; rr < 4; rr++) {
            const int row = warp * 4 + rr;
            const float thr = rthr[row];
            const float* xr = sxf + row * D_DIM;
            const __half* drow = dist + row * DPITCH_H + lane * 16;

            uint4 w0 = *(const uint4*)(drow);        // codes lane*16 .. +7
            uint4 w1 = *(const uint4*)(drow + 8);    // codes lane*16+8 .. +15
            float ev = 3.4e38f; int ek = 0x7fffffff;
            const uint32_t ws[8] = { w0.x, w0.y, w0.z, w0.w, w1.x, w1.y, w1.z, w1.w };
            #pragma unroll
            for (int q = 0; q < 8; q++) {
                float2 f = __half22float2(*(const __half2*)&ws[q]);
                int k0 = lane * 16 + q * 2;
                float sa = f.x + se2s[k0];
                float sb = f.y + se2s[k0 + 1];
                if (sa <= thr) {
                    float s = exact_dist(xr, k0, se2s[k0]);
                    if (s < ev || (s == ev && k0 < ek)) { ev = s; ek = k0; }
                }
                if (sb <= thr) {
                    float s = exact_dist(xr, k0 + 1, se2s[k0 + 1]);
                    if (s < ev || (s == ev && k0 + 1 < ek)) { ev = s; ek = k0 + 1; }
                }
            }
            #pragma unroll
            for (int off = 16; off; off >>= 1) {
                float ov = __shfl_xor_sync(0xffffffffu, ev, off);
                int   ok = __shfl_xor_sync(0xffffffffu, ek, off);
                if (ov < ev || (ov == ev && ok < ek)) { ev = ov; ek = ok; }
            }
            if (lane == 0) kfin[row] = ek;
        }
        __syncthreads();

        // ---- gather exact E row + store (4 threads/row x 16 floats) ----
        if (tid < TILE_ROWS * 4) {
            int row = tid >> 2, part = tid & 3;
            int grow = rowbase + row;
            if (grow < nrows) {
                const float4* src = (const float4*)(g_Et + kfin[row] * D_DIM + part * 16);
                float4* dst = (float4*)(out + (size_t)grow * D_DIM + part * 16);
                dst[0] = src[0]; dst[1] = src[1]; dst[2] = src[2]; dst[3] = src[3];
            }
        }
        __syncthreads();   // smem reuse guard for next tile
    }
}

extern "C" void kernel_launch(void* const* d_in, const int* in_sizes, int n_in,
                              void* d_out, int out_size)
{
    const float* x   = (const float*)d_in[0];   // inputs [B,H,W,D] fp32
    const float* emb = (const float*)d_in[1];   // embeddings [D,K] fp32
    float* out = (float*)d_out;

    int nrows  = in_sizes[0] / D_DIM;
    int ntiles = (nrows + TILE_ROWS - 1) / TILE_ROWS;

    vq_prep<<<(K_DIM * D_DIM + 511) / 512, 512>>>(emb);

    cudaFuncSetAttribute(vq_main, cudaFuncAttributeMaxDynamicSharedMemorySize, SM_TOTAL);
    int grid = NBLOCKS;
    if (grid > ntiles) grid = ntiles;
    vq_main<<<grid, THREADS, SM_TOTAL>>>(x, emb, out, nrows, ntiles);
}

// round 15
// speedup vs baseline: 1.8319x; 1.0028x over previous
#include <cuda_runtime.h>
#include <cuda_fp16.h>
#include <cstdint>

#define D_DIM 64
#define K_DIM 512
#define TILE_ROWS 64
#define THREADS 512
#define NBLOCKS 148
#define MARGIN 1.0f
#define DPITCH_H 520     // dist pitch in halves (1040 B)

// ---------------- device scratch (no cudaMalloc allowed) ----------------
__device__ float g_Et[K_DIM * D_DIM];    // exact fp32 E, code-major [k][d]

// ---------------- smem layout (bytes) ----------------
#define SM_EH    0                                    // [64][512] half  = 65536
#define SM_XH    (SM_EH + D_DIM * K_DIM * 2)          // [64][64] half2  = 16384 (dup -2x)
#define SM_XF    (SM_XH + TILE_ROWS * D_DIM * 4)      // [64][64] f32    = 16384
#define SM_SE2   (SM_XF + TILE_ROWS * D_DIM * 4)      // [512] f32       = 2048
#define SM_PVAL  (SM_SE2 + K_DIM * 4)                 // [2][64] f32     = 512
#define SM_RTHR  (SM_PVAL + 512)                      // [64] f32        = 256
#define SM_KFIN  (SM_RTHR + 256)                      // [64] i32        = 256
#define SM_DIST  (SM_KFIN + 256)                      // [64][520] half  = 66560
#define SM_TOTAL (SM_DIST + TILE_ROWS * DPITCH_H * 2) // 167936

// ---------------- prep: transpose E to code-major ----------------
__global__ void vq_prep(const float* __restrict__ emb) {
    int i = blockIdx.x * blockDim.x + threadIdx.x;
    if (i < K_DIM * D_DIM) {
        int k = i / D_DIM, d = i % D_DIM;
        g_Et[i] = emb[d * K_DIM + k];
    }
}

// exact fp32 distance: x row from smem, E row from gmem (L2-hot)
__device__ __forceinline__ float exact_dist(const float* xr, int k, float se2k) {
    const float4* er = (const float4*)(g_Et + k * D_DIM);
    const float4* x4 = (const float4*)xr;
    float d0 = 0.f, d1 = 0.f;
    #pragma unroll 4
    for (int q = 0; q < 16; q += 2) {
        float4 ea = er[q],     xa = x4[q];
        float4 eb = er[q + 1], xb = x4[q + 1];
        d0 = fmaf(xa.x, ea.x, d0); d0 = fmaf(xa.y, ea.y, d0);
        d0 = fmaf(xa.z, ea.z, d0); d0 = fmaf(xa.w, ea.w, d0);
        d1 = fmaf(xb.x, eb.x, d1); d1 = fmaf(xb.y, eb.y, d1);
        d1 = fmaf(xb.z, eb.z, d1); d1 = fmaf(xb.w, eb.w, d1);
    }
    return fmaf(-2.f, d0 + d1, se2k);
}

// ---------------- main ----------------
__global__ void __launch_bounds__(THREADS, 1)
vq_main(const float* __restrict__ x, const float* __restrict__ emb,
        float* __restrict__ out, int nrows, int ntiles)
{
    extern __shared__ char smem[];
    __half*  sEh  = (__half*) (smem + SM_EH);    // [d][k] fp16 codebook
    __half2* sxh  = (__half2*)(smem + SM_XH);    // [row][d] dup {-2x,-2x}
    float*   sxf  = (float*)  (smem + SM_XF);    // [row][d] exact x
    float*   se2s = (float*)  (smem + SM_SE2);
    float*   pval = (float*)  (smem + SM_PVAL);  // [2][64]
    float*   rthr = (float*)  (smem + SM_RTHR);
    int*     kfin = (int*)    (smem + SM_KFIN);
    __half*  dist = (__half*) (smem + SM_DIST);  // raw -2x.e accumulators

    const int tid  = threadIdx.x;
    const int warp = tid >> 5;
    const int lane = tid & 31;
    const int g    = warp & 7;            // row group: rows g*8..+7
    const int h    = warp >> 3;           // K half: codes h*256..+255
    const int r0   = g * 8;
    const int kbase = h * 256 + lane * 8; // lane owns 8 consecutive codes

    // ---- one-time: fp16 codebook (emb is already [d][k]) + exact ||e||^2 ----
    for (int i = tid; i < D_DIM * K_DIM / 4; i += THREADS) {
        float4 v = *(const float4*)(emb + i * 4);
        __half2 h0 = __floats2half2_rn(v.x, v.y);
        __half2 h1 = __floats2half2_rn(v.z, v.w);
        uint2 pk;
        pk.x = *(uint32_t*)&h0; pk.y = *(uint32_t*)&h1;
        *(uint2*)(sEh + i * 4) = pk;
    }
    {
        const float* er = g_Et + tid * D_DIM;    // THREADS == K_DIM
        float s = 0.f;
        #pragma unroll 8
        for (int d = 0; d < D_DIM; d++) s = fmaf(er[d], er[d], s);
        se2s[tid] = s;
    }
    __syncthreads();

    for (int tile = blockIdx.x; tile < ntiles; tile += gridDim.x) {
        const int rowbase = tile * TILE_ROWS;

        // ---- load x tile: exact fp32 + dup'd fp16 (-2x) ----
        for (int i = tid; i < TILE_ROWS * D_DIM / 4; i += THREADS) {
            int row = i >> 4, d4 = (i & 15) * 4;
            int grow = rowbase + row;
            float4 v = (grow < nrows) ? *(const float4*)(x + (size_t)grow * D_DIM + d4)
                                      : make_float4(0.f, 0.f, 0.f, 0.f);
            *(float4*)(sxf + row * D_DIM + d4) = v;
            __half2 a = __floats2half2_rn(-2.f * v.x, -2.f * v.x);
            __half2 b = __floats2half2_rn(-2.f * v.y, -2.f * v.y);
            __half2 c = __floats2half2_rn(-2.f * v.z, -2.f * v.z);
            __half2 e = __floats2half2_rn(-2.f * v.w, -2.f * v.w);
            uint4 pk;
            pk.x = *(uint32_t*)&a; pk.y = *(uint32_t*)&b;
            pk.z = *(uint32_t*)&c; pk.w = *(uint32_t*)&e;
            *(uint4*)(sxh + row * D_DIM + d4) = pk;
        }
        __syncthreads();

        // ---- HFMA2 mainloop: warp = 8 rows x 256 codes, lane = 8 codes ----
        // d-pair blocks: stage 8 x-loads (uint2 = 2 dup'd half2) + 2 E-loads
        // (uint4) BEFORE the 64-HFMA2 burst -> LDS latency hidden, high ILP.
        __half2 acc[8][4];
        const __half2 z = __floats2half2_rn(0.f, 0.f);
        #pragma unroll
        for (int r = 0; r < 8; r++) {
            acc[r][0] = z; acc[r][1] = z; acc[r][2] = z; acc[r][3] = z;
        }

        const __half* ebase = sEh + kbase;
        #pragma unroll 2
        for (int d0 = 0; d0 < D_DIM; d0 += 2) {
            uint2 xw[8];
            #pragma unroll
            for (int r = 0; r < 8; r++)
                xw[r] = *(const uint2*)(sxh + (r0 + r) * D_DIM + d0);   // broadcast LDS.64

            uint4 ew0 = *(const uint4*)(ebase + d0 * K_DIM);            // 8 codes @ d0
            uint4 ew1 = *(const uint4*)(ebase + (d0 + 1) * K_DIM);      // 8 codes @ d0+1

            __half2 e00 = *(__half2*)&ew0.x, e01 = *(__half2*)&ew0.y;
            __half2 e02 = *(__half2*)&ew0.z, e03 = *(__half2*)&ew0.w;
            __half2 e10 = *(__half2*)&ew1.x, e11 = *(__half2*)&ew1.y;
            __half2 e12 = *(__half2*)&ew1.z, e13 = *(__half2*)&ew1.w;

            #pragma unroll
            for (int r = 0; r < 8; r++) {
                __half2 x0 = *(__half2*)&xw[r].x;   // dup(-2x[d0])
                __half2 x1 = *(__half2*)&xw[r].y;   // dup(-2x[d0+1])
                acc[r][0] = __hfma2(e00, x0, acc[r][0]);
                acc[r][1] = __hfma2(e01, x0, acc[r][1]);
                acc[r][2] = __hfma2(e02, x0, acc[r][2]);
                acc[r][3] = __hfma2(e03, x0, acc[r][3]);
                acc[r][0] = __hfma2(e10, x1, acc[r][0]);
                acc[r][1] = __hfma2(e11, x1, acc[r][1]);
                acc[r][2] = __hfma2(e12, x1, acc[r][2]);
                acc[r][3] = __hfma2(e13, x1, acc[r][3]);
            }
        }

        // store raw accumulators to dist (16B per row per lane, conflict-free)
        // and track per-lane approx best VALUE per row
        float bestv[8];
        {
            float4 s2a = *(const float4*)(se2s + kbase);
            float4 s2b = *(const float4*)(se2s + kbase + 4);
            #pragma unroll
            for (int r = 0; r < 8; r++) {
                uint4 pk;
                pk.x = *(uint32_t*)&acc[r][0]; pk.y = *(uint32_t*)&acc[r][1];
                pk.z = *(uint32_t*)&acc[r][2]; pk.w = *(uint32_t*)&acc[r][3];
                *(uint4*)(dist + (r0 + r) * DPITCH_H + kbase) = pk;

                float2 f0 = __half22float2(acc[r][0]);
                float2 f1 = __half22float2(acc[r][1]);
                float2 f2 = __half22float2(acc[r][2]);
                float2 f3 = __half22float2(acc[r][3]);
                float m = fminf(fminf(f0.x + s2a.x, f0.y + s2a.y),
                                fminf(f1.x + s2a.z, f1.y + s2a.w));
                m = fminf(m, fminf(fminf(f2.x + s2b.x, f2.y + s2b.y),
                                   fminf(f3.x + s2b.z, f3.y + s2b.w)));
                bestv[r] = m;
            }
        }
        // per-row warp-reduce best value; write pval[h][row]
        #pragma unroll
        for (int r = 0; r < 8; r++) {
            float mv = bestv[r];
            #pragma unroll
            for (int off = 16; off; off >>= 1)
                mv = fminf(mv, __shfl_xor_sync(0xffffffffu, mv, off));
            if (lane == 0) pval[h * 64 + r0 + r] = mv;
        }
        __syncthreads();

        // merge the two K-halves -> per-row threshold
        if (tid < TILE_ROWS)
            rthr[tid] = fminf(pval[tid], pval[64 + tid]) + MARGIN;
        __syncthreads();

        // ---- scan: candidates from stored scores, exact fp32 rescore ----
        // warp -> 4 rows; lane -> 16 codes of that row
        for (int rr = 0; rr < 4; rr++) {
            const int row = warp * 4 + rr;
            const float thr = rthr[row];
            const float* xr = sxf + row * D_DIM;
            const __half* drow = dist + row * DPITCH_H + lane * 16;

            uint4 w0 = *(const uint4*)(drow);        // codes lane*16 .. +7
            uint4 w1 = *(const uint4*)(drow + 8);    // codes lane*16+8 .. +15
            float ev = 3.4e38f; int ek = 0x7fffffff;
            const uint32_t ws[8] = { w0.x, w0.y, w0.z, w0.w, w1.x, w1.y, w1.z, w1.w };
            #pragma unroll
            for (int q = 0; q < 8; q++) {
                float2 f = __half22float2(*(const __half2*)&ws[q]);
                int k0 = lane * 16 + q * 2;
                float sa = f.x + se2s[k0];
                float sb = f.y + se2s[k0 + 1];
                if (sa <= thr) {
                    float s = exact_dist(xr, k0, se2s[k0]);
                    if (s < ev || (s == ev && k0 < ek)) { ev = s; ek = k0; }
                }
                if (sb <= thr) {
                    float s = exact_dist(xr, k0 + 1, se2s[k0 + 1]);
                    if (s < ev || (s == ev && k0 + 1 < ek)) { ev = s; ek = k0 + 1; }
                }
            }
            #pragma unroll
            for (int off = 16; off; off >>= 1) {
                float ov = __shfl_xor_sync(0xffffffffu, ev, off);
                int   ok = __shfl_xor_sync(0xffffffffu, ek, off);
                if (ov < ev || (ov == ev && ok < ek)) { ev = ov; ek = ok; }
            }
            if (lane == 0) kfin[row] = ek;
        }
        __syncthreads();

        // ---- gather exact E row + store (4 threads/row x 16 floats) ----
        if (tid < TILE_ROWS * 4) {
            int row = tid >> 2, part = tid & 3;
            int grow = rowbase + row;
            if (grow < nrows) {
                const float4* src = (const float4*)(g_Et + kfin[row] * D_DIM + part * 16);
                float4* dst = (float4*)(out + (size_t)grow * D_DIM + part * 16);
                dst[0] = src[0]; dst[1] = src[1]; dst[2] = src[2]; dst[3] = src[3];
            }
        }
        __syncthreads();   // smem reuse guard for next tile
    }
}

extern "C" void kernel_launch(void* const* d_in, const int* in_sizes, int n_in,
                              void* d_out, int out_size)
{
    const float* x   = (const float*)d_in[0];   // inputs [B,H,W,D] fp32
    const float* emb = (const float*)d_in[1];   // embeddings [D,K] fp32
    float* out = (float*)d_out;

    int nrows  = in_sizes[0] / D_DIM;
    int ntiles = (nrows + TILE_ROWS - 1) / TILE_ROWS;

    vq_prep<<<(K_DIM * D_DIM + 511) / 512, 512>>>(emb);

    cudaFuncSetAttribute(vq_main, cudaFuncAttributeMaxDynamicSharedMemorySize, SM_TOTAL);
    int grid = NBLOCKS;
    if (grid > ntiles) grid = ntiles;
    vq_main<<<grid, THREADS, SM_TOTAL>>>(x, emb, out, nrows, ntiles);
}